// round 9
// baseline (speedup 1.0000x reference)
#include <cuda_runtime.h>
#include <cuda_bf16.h>
#include <stdint.h>

// ---------------- problem constants ----------------
#define BATCH 8
#define NTOK 4096
#define DIM 768
#define SIM_THRESH 0.2f
#define COS_EPS 1e-8f

// int8 quantization: q = round(v * 127/0.3), sim ~= acc * (0.3/127)^2
#define QSCALE (127.0f / 0.3f)
#define ITHRESH 30000   // acc > 30000 <=> sim > ~0.167 (filter; exact rescore follows)

// ---------------- capacities ----------------
#define CCAP 32768      // global candidate capacity
#define PC2 64          // per-doc pair cap (both directions)
#define RC2 32          // per-doc special-row cap

// ---------------- detector tiling (proven R6 config) ----------------
#define BM 128
#define BN 128
#define BKB 64                 // BYTES of K per chunk per row
#define KITER (DIM / BKB)      // 12
#define STAGES 3

// ---------------- device scratch ----------------
__device__ int8_t g_q[(size_t)BATCH * NTOK * DIM];            // quantized normalized rows (~25MB)
__device__ float g_inv[BATCH * NTOK];                         // 1/norm per row
__device__ float g_WT[3][DIM * DIM];                          // W^T
__device__ int g_cd[CCAP];
__device__ int g_ci[CCAP];
__device__ int g_cj[CCAP];
__device__ int g_cc;
__device__ float g_h[2][BATCH][RC2][DIM];                     // special-row activations

// ---------------- helpers ----------------
__device__ __forceinline__ uint32_t smem_u32(const void* p) {
    uint32_t a;
    asm("{ .reg .u64 t; cvta.to.shared.u64 t, %1; cvt.u32.u64 %0, t; }" : "=r"(a) : "l"(p));
    return a;
}
#define SW64(off) ((off) ^ (((off) >> 3) & 0x30))

__device__ __forceinline__ void cp16(uint32_t dst, const void* src) {
    asm volatile("cp.async.cg.shared.global [%0], [%1], 16;" :: "r"(dst), "l"(src) : "memory");
}
#define CP_COMMIT() asm volatile("cp.async.commit_group;" ::: "memory")
#define CP_WAIT1()  asm volatile("cp.async.wait_group 1;" ::: "memory")

__device__ __forceinline__ void ldm_x4(uint32_t& r0, uint32_t& r1, uint32_t& r2, uint32_t& r3, uint32_t addr) {
    asm volatile("ldmatrix.sync.aligned.m8n8.x4.shared.b16 {%0,%1,%2,%3}, [%4];"
                 : "=r"(r0), "=r"(r1), "=r"(r2), "=r"(r3) : "r"(addr));
}
__device__ __forceinline__ void imma16832(int* c, const uint32_t* a, const uint32_t* b) {
    asm volatile("mma.sync.aligned.m16n8k32.row.col.s32.s8.s8.s32 "
                 "{%0,%1,%2,%3}, {%4,%5,%6,%7}, {%8,%9}, {%0,%1,%2,%3};"
                 : "+r"(c[0]), "+r"(c[1]), "+r"(c[2]), "+r"(c[3])
                 : "r"(a[0]), "r"(a[1]), "r"(a[2]), "r"(a[3]), "r"(b[0]), "r"(b[1]));
}

// ---------------- kernel 1: normalize -> int8 + weight transpose (fused) ----------------
// blocks [0, NORMB): one warp per row (8 rows/block)
// blocks [NORMB, NORMB+3*24*24): 32x32 transpose tiles
#define NORMB ((BATCH * NTOK) / 8)
#define TTILES ((DIM / 32) * (DIM / 32))   // 576

__global__ void knormtrans(const float* __restrict__ emb,
                           const float* __restrict__ W1, const float* __restrict__ W2,
                           const float* __restrict__ W3) {
    int b = blockIdx.x, t = threadIdx.x;
    if (b < NORMB) {
        int gw = (b * 256 + t) >> 5;      // global warp = row
        int lane = t & 31;
        if (gw == 0 && lane == 0) g_cc = 0;
        const float4* e4 = (const float4*)(emb + (size_t)gw * DIM);
        float4 v[6];
        float ss = 0.f;
#pragma unroll
        for (int u = 0; u < 6; u++) {
            v[u] = e4[u * 32 + lane];
            ss += v[u].x * v[u].x + v[u].y * v[u].y + v[u].z * v[u].z + v[u].w * v[u].w;
        }
#pragma unroll
        for (int o = 16; o > 0; o >>= 1) ss += __shfl_xor_sync(0xffffffffu, ss, o);
        float inv = 1.0f / fmaxf(sqrtf(ss), COS_EPS);
        if (lane == 0) g_inv[gw] = inv;
        float s = inv * QSCALE;
        char4* q4 = (char4*)(g_q + (size_t)gw * DIM);
#pragma unroll
        for (int u = 0; u < 6; u++) {
            char4 q;
            q.x = (char)__float2int_rn(fmaxf(fminf(v[u].x * s, 127.f), -127.f));
            q.y = (char)__float2int_rn(fmaxf(fminf(v[u].y * s, 127.f), -127.f));
            q.z = (char)__float2int_rn(fmaxf(fminf(v[u].z * s, 127.f), -127.f));
            q.w = (char)__float2int_rn(fmaxf(fminf(v[u].w * s, 127.f), -127.f));
            q4[u * 32 + lane] = q;
        }
    } else {
        __shared__ float s[32][33];
        int bb = b - NORMB;
        int m = bb / TTILES;
        int rem = bb % TTILES;
        int kx = rem % (DIM / 32), oy = rem / (DIM / 32);
        const float* W = (m == 0) ? W1 : (m == 1 ? W2 : W3);
        int tx = t & 31, ty = t >> 5;    // 32 x 8
        int k0 = kx * 32, o0 = oy * 32;
#pragma unroll
        for (int j = 0; j < 32; j += 8)
            s[ty + j][tx] = W[(size_t)(o0 + ty + j) * DIM + (k0 + tx)];
        __syncthreads();
#pragma unroll
        for (int j = 0; j < 32; j += 8)
            g_WT[m][(size_t)(k0 + ty + j) * DIM + (o0 + tx)] = s[tx][ty + j];
    }
}

// ---------------- kernel 2: int8 detector (proven R6 config) ----------------
__global__ void __launch_bounds__(256, 2) kdet() {
    int lin = blockIdx.x, d = blockIdx.z;
    int bx = (int)((sqrtf(8.f * (float)lin + 1.f) - 1.f) * 0.5f);
    while ((bx + 1) * (bx + 2) / 2 <= lin) bx++;
    while (bx * (bx + 1) / 2 > lin) bx--;
    int by = lin - bx * (bx + 1) / 2;

    __shared__ __align__(128) unsigned char As[STAGES][BM * BKB];
    __shared__ __align__(128) unsigned char Bs[STAGES][BM * BKB];

    int t = threadIdx.x, wid = t >> 5, lane = t & 31;
    int wm = wid & 1;        // 2 warps along M (64 rows each)
    int wn = wid >> 1;       // 4 warps along N (32 cols each)

    const int8_t* Ag = g_q + ((size_t)d * NTOK + (size_t)bx * BM) * DIM;
    const int8_t* Bg = g_q + ((size_t)d * NTOK + (size_t)by * BN) * DIM;

    uint32_t AsA[STAGES], BsA[STAGES];
#pragma unroll
    for (int s = 0; s < STAGES; s++) { AsA[s] = smem_u32(As[s]); BsA[s] = smem_u32(Bs[s]); }

    int rowq[2], segq[2];
    uint32_t soffq[2];
#pragma unroll
    for (int u = 0; u < 2; u++) {
        int q = t + 256 * u;
        rowq[u] = q >> 2; segq[u] = q & 3;
        soffq[u] = SW64((uint32_t)(rowq[u] * 64 + segq[u] * 16));
    }

#pragma unroll
    for (int s = 0; s < STAGES - 1; s++) {
        int k0 = s * BKB;
#pragma unroll
        for (int u = 0; u < 2; u++) {
            cp16(AsA[s] + soffq[u], Ag + (size_t)rowq[u] * DIM + k0 + segq[u] * 16);
            cp16(BsA[s] + soffq[u], Bg + (size_t)rowq[u] * DIM + k0 + segq[u] * 16);
        }
        CP_COMMIT();
    }

    int acc[4][4][4];
#pragma unroll
    for (int mi = 0; mi < 4; mi++)
#pragma unroll
        for (int ni = 0; ni < 4; ni++)
#pragma unroll
            for (int e = 0; e < 4; e++) acc[mi][ni][e] = 0;

    int cur = 0;
    for (int kb = 0; kb < KITER; kb++) {
        CP_WAIT1();
        __syncthreads();
        int nk = kb + STAGES - 1;
        if (nk < KITER) {
            int s = nk % STAGES;
            int k0 = nk * BKB;
#pragma unroll
            for (int u = 0; u < 2; u++) {
                cp16(AsA[s] + soffq[u], Ag + (size_t)rowq[u] * DIM + k0 + segq[u] * 16);
                cp16(BsA[s] + soffq[u], Bg + (size_t)rowq[u] * DIM + k0 + segq[u] * 16);
            }
        }
        CP_COMMIT();

#pragma unroll
        for (int ks = 0; ks < 2; ks++) {
            uint32_t af[4][4];
#pragma unroll
            for (int mi = 0; mi < 4; mi++) {
                int row = wm * 64 + mi * 16 + (lane & 15);
                int bcol = ks * 32 + ((lane >> 4) << 4);
                uint32_t addr = AsA[cur] + SW64((uint32_t)(row * 64 + bcol));
                ldm_x4(af[mi][0], af[mi][1], af[mi][2], af[mi][3], addr);
            }
            uint32_t bfr[4][2];
#pragma unroll
            for (int pair = 0; pair < 2; pair++) {
                int g = lane >> 3;
                int row = wn * 32 + pair * 16 + ((g >> 1) << 3) + (lane & 7);
                int bcol = ks * 32 + ((g & 1) << 4);
                uint32_t addr = BsA[cur] + SW64((uint32_t)(row * 64 + bcol));
                uint32_t r0, r1, r2, r3;
                ldm_x4(r0, r1, r2, r3, addr);
                bfr[pair * 2][0] = r0; bfr[pair * 2][1] = r1;
                bfr[pair * 2 + 1][0] = r2; bfr[pair * 2 + 1][1] = r3;
            }
#pragma unroll
            for (int mi = 0; mi < 4; mi++)
#pragma unroll
                for (int ni = 0; ni < 4; ni++)
                    imma16832(acc[mi][ni], af[mi], bfr[ni]);
        }
        cur = (cur + 1) % STAGES;
    }

    int i_base = bx * BM + wm * 64;
    int j_base = by * BN + wn * 32;
#pragma unroll
    for (int mi = 0; mi < 4; mi++) {
#pragma unroll
        for (int ni = 0; ni < 4; ni++) {
#pragma unroll
            for (int e = 0; e < 4; e++) {
                if (acc[mi][ni][e] > ITHRESH) {
                    int i = i_base + mi * 16 + (lane >> 2) + ((e >> 1) << 3);
                    int j = j_base + ni * 8 + ((lane & 3) << 1) + (e & 1);
                    if (i > j) {
                        int idx = atomicAdd(&g_cc, 1);
                        if (idx < CCAP) { g_cd[idx] = d; g_ci[idx] = i; g_cj[idx] = j; }
                    }
                }
            }
        }
    }
}

// ---------------- kernel 3: fused tail (rescore + prep + 3 layers + output) ----------------
// grid = BATCH, block = 256
__global__ void ktail(const float* __restrict__ emb,
                      const float* __restrict__ b1, const float* __restrict__ b2,
                      const float* __restrict__ b3, float* __restrict__ out) {
    int d = blockIdx.x, t = threadIdx.x, wid = t >> 5, lane = t & 31;

    __shared__ float y[DIM];
    __shared__ int   cidx[PC2];
    __shared__ float csim[PC2];
    __shared__ int   pi2[PC2], pj2[PC2];
    __shared__ float ps2[PC2];
    __shared__ int   rows2[RC2], rowptr2[RC2 + 1], jx2[PC2];
    __shared__ int   s_nc, s_np, s_ns;

    // ---- stage 1: collect this doc's candidates ----
    if (t == 0) {
        int C = g_cc; if (C > CCAP) C = CCAP;
        int n = 0;
        for (int c = 0; c < C && n < PC2 / 2; c++)
            if (g_cd[c] == d) cidx[n++] = c;
        s_nc = n;
    }
    __syncthreads();

    // ---- stage 2: exact fp32 rescore (one warp per candidate) ----
    int nc = s_nc;
    for (int cc = wid; cc < nc; cc += 8) {
        int i = g_ci[cidx[cc]], j = g_cj[cidx[cc]];
        const float* ei = emb + ((size_t)d * NTOK + i) * DIM;
        const float* ej = emb + ((size_t)d * NTOK + j) * DIM;
        float a = 0.f;
        for (int k = lane; k < DIM; k += 32) a += ei[k] * ej[k];
#pragma unroll
        for (int o = 16; o > 0; o >>= 1) a += __shfl_xor_sync(0xffffffffu, a, o);
        if (lane == 0)
            csim[cc] = a * g_inv[d * NTOK + i] * g_inv[d * NTOK + j];
    }
    __syncthreads();

    // ---- stage 3: build pair list (both dirs), sort, csr (thread 0; np tiny) ----
    if (t == 0) {
        int np = 0;
        for (int cc = 0; cc < nc; cc++) {
            float s = csim[cc];
            if (s > SIM_THRESH) {
                int i = g_ci[cidx[cc]], j = g_cj[cidx[cc]];
                pi2[np] = i; pj2[np] = j; ps2[np] = s; np++;
                pi2[np] = j; pj2[np] = i; ps2[np] = s; np++;
            }
        }
        // insertion sort by (i, j)
        for (int a = 1; a < np; a++) {
            int ii = pi2[a], jj = pj2[a]; float ss = ps2[a];
            long key = (long)ii * NTOK + jj;
            int b = a - 1;
            while (b >= 0 && (long)pi2[b] * NTOK + pj2[b] > key) {
                pi2[b + 1] = pi2[b]; pj2[b + 1] = pj2[b]; ps2[b + 1] = ps2[b]; b--;
            }
            pi2[b + 1] = ii; pj2[b + 1] = jj; ps2[b + 1] = ss;
        }
        // unique rows + csr
        int ns = 0;
        for (int p = 0; p < np; p++) {
            if (ns == 0 || rows2[ns - 1] != pi2[p]) {
                if (ns < RC2) { rows2[ns] = pi2[p]; rowptr2[ns] = p; ns++; }
            }
        }
        rowptr2[ns] = np;
        // per-pair source row index (binary search over rows2)
        for (int p = 0; p < np; p++) {
            int lo = 0, hi = ns - 1, f = -1, v = pj2[p];
            while (lo <= hi) {
                int mid = (lo + hi) >> 1; int rv = rows2[mid];
                if (rv == v) { f = mid; break; }
                if (rv < v) lo = mid + 1; else hi = mid - 1;
            }
            jx2[p] = f;
        }
        s_np = np; s_ns = ns;
    }
    __syncthreads();

    int ns = s_ns;
    const float* bs[3] = {b1, b2, b3};

    // ---- stage 4: three GNN layers on special rows ----
    for (int l = 0; l < 3; l++) {
        const float* WT = g_WT[l];
        const float* bprev = (l > 0) ? bs[l - 1] : b1;   // unused for l==0
        int rd = (l + 1) & 1;
        int wr = l & 1;
        for (int ii = 0; ii < ns; ii++) {
            int p0 = rowptr2[ii], p1 = rowptr2[ii + 1];
            for (int k = t; k < DIM; k += 256) {
                float a = 0.f;
                for (int p = p0; p < p1; p++) {
                    float v;
                    if (l == 0) {
                        v = emb[((size_t)d * NTOK + pj2[p]) * DIM + k];
                    } else {
                        int jx = jx2[p];
                        v = (jx >= 0) ? g_h[rd][d][jx][k] : fmaxf(bprev[k], 0.f);
                    }
                    a += ps2[p] * v;
                }
                y[k] = a;
            }
            __syncthreads();
            // matvec: each thread covers 3 outputs
#pragma unroll
            for (int u = 0; u < 3; u++) {
                int c = t + u * 256;
                float a = bs[l][c];
#pragma unroll 16
                for (int k = 0; k < DIM; k++) a = fmaf(y[k], WT[(size_t)k * DIM + c], a);
                g_h[wr][d][ii][c] = fmaxf(a, 0.f);
            }
            __syncthreads();
        }
    }

    // ---- stage 5: output mean ----
#pragma unroll
    for (int u = 0; u < 3; u++) {
        int c = t + u * 256;
        float c3 = fmaxf(b3[c], 0.f);
        float a = c3;
        for (int ii = 0; ii < ns; ii++)
            a += (g_h[0][d][ii][c] - c3) * (1.0f / (float)NTOK);
        out[(size_t)d * DIM + c] = a;
    }
}

// ---------------- launch ----------------
extern "C" void kernel_launch(void* const* d_in, const int* in_sizes, int n_in,
                              void* d_out, int out_size) {
    const float* emb = (const float*)d_in[0];
    const float* W1  = (const float*)d_in[1];
    const float* b1  = (const float*)d_in[2];
    const float* W2  = (const float*)d_in[3];
    const float* b2  = (const float*)d_in[4];
    const float* W3  = (const float*)d_in[5];
    const float* b3  = (const float*)d_in[6];
    float* out = (float*)d_out;

    knormtrans<<<NORMB + 3 * TTILES, 256>>>(emb, W1, W2, W3);
    int nblk = NTOK / BM;                       // 32
    dim3 g(nblk * (nblk + 1) / 2, 1, BATCH);    // 528 x 8
    kdet<<<g, 256>>>();
    ktail<<<BATCH, 256>>>(emb, b1, b2, b3, out);
}

// round 10
// speedup vs baseline: 3.1439x; 3.1439x over previous
#include <cuda_runtime.h>
#include <cuda_bf16.h>
#include <stdint.h>

// ---------------- problem constants ----------------
#define BATCH 8
#define NTOK 4096
#define DIM 768
#define SIM_THRESH 0.2f
#define COS_EPS 1e-8f

// int8 quantization: q = round(v * 127/0.3), sim ~= acc * (0.3/127)^2
#define QSCALE (127.0f / 0.3f)
#define ITHRESH 30000   // acc > 30000 <=> sim > ~0.167 (filter; exact rescore follows)

// ---------------- capacities ----------------
#define CCAP 32768
#define DCAP 1024
#define RCAP 512

// ---------------- detector tiling (proven R6 config) ----------------
#define BM 128
#define BN 128
#define BKB 64                 // BYTES of K per chunk per row
#define KITER (DIM / BKB)      // 12
#define STAGES 3

// ---------------- device scratch ----------------
__device__ int8_t g_q[(size_t)BATCH * NTOK * DIM];            // quantized normalized rows (~25MB)
__device__ float g_inv[BATCH * NTOK];                         // 1/norm per row
__device__ float g_WT[3][DIM * DIM];                          // W^T
// candidates (int filter)
__device__ int g_cd[CCAP];
__device__ int g_ci[CCAP];
__device__ int g_cj[CCAP];
__device__ int g_cc;
// per-doc sparse metadata
__device__ int   g_ns[BATCH];
__device__ int   g_dpj[BATCH][DCAP];
__device__ float g_dps[BATCH][DCAP];
__device__ int   g_djx[BATCH][DCAP];
__device__ int   g_rows[BATCH][RCAP];
__device__ int   g_rowptr[BATCH][RCAP + 1];
// activations for special rows
__device__ float g_h[2][BATCH][RCAP][DIM];

// ---------------- helpers ----------------
__device__ __forceinline__ uint32_t smem_u32(const void* p) {
    uint32_t a;
    asm("{ .reg .u64 t; cvta.to.shared.u64 t, %1; cvt.u32.u64 %0, t; }" : "=r"(a) : "l"(p));
    return a;
}
#define SW64(off) ((off) ^ (((off) >> 3) & 0x30))

__device__ __forceinline__ void cp16(uint32_t dst, const void* src) {
    asm volatile("cp.async.cg.shared.global [%0], [%1], 16;" :: "r"(dst), "l"(src) : "memory");
}
#define CP_COMMIT() asm volatile("cp.async.commit_group;" ::: "memory")
#define CP_WAIT1()  asm volatile("cp.async.wait_group 1;" ::: "memory")

__device__ __forceinline__ void ldm_x4(uint32_t& r0, uint32_t& r1, uint32_t& r2, uint32_t& r3, uint32_t addr) {
    asm volatile("ldmatrix.sync.aligned.m8n8.x4.shared.b16 {%0,%1,%2,%3}, [%4];"
                 : "=r"(r0), "=r"(r1), "=r"(r2), "=r"(r3) : "r"(addr));
}
__device__ __forceinline__ void imma16832(int* c, const uint32_t* a, const uint32_t* b) {
    asm volatile("mma.sync.aligned.m16n8k32.row.col.s32.s8.s8.s32 "
                 "{%0,%1,%2,%3}, {%4,%5,%6,%7}, {%8,%9}, {%0,%1,%2,%3};"
                 : "+r"(c[0]), "+r"(c[1]), "+r"(c[2]), "+r"(c[3])
                 : "r"(a[0]), "r"(a[1]), "r"(a[2]), "r"(a[3]), "r"(b[0]), "r"(b[1]));
}

// ---------------- kernel 1: normalize -> int8 + weight transpose (fused; validated R9) ----------------
#define NORMB ((BATCH * NTOK) / 8)
#define TTILES ((DIM / 32) * (DIM / 32))   // 576

__global__ void knormtrans(const float* __restrict__ emb,
                           const float* __restrict__ W1, const float* __restrict__ W2,
                           const float* __restrict__ W3) {
    int b = blockIdx.x, t = threadIdx.x;
    if (b < NORMB) {
        int gw = (b * 256 + t) >> 5;      // global warp = row
        int lane = t & 31;
        if (gw == 0 && lane == 0) g_cc = 0;
        const float4* e4 = (const float4*)(emb + (size_t)gw * DIM);
        float4 v[6];
        float ss = 0.f;
#pragma unroll
        for (int u = 0; u < 6; u++) {
            v[u] = e4[u * 32 + lane];
            ss += v[u].x * v[u].x + v[u].y * v[u].y + v[u].z * v[u].z + v[u].w * v[u].w;
        }
#pragma unroll
        for (int o = 16; o > 0; o >>= 1) ss += __shfl_xor_sync(0xffffffffu, ss, o);
        float inv = 1.0f / fmaxf(sqrtf(ss), COS_EPS);
        if (lane == 0) g_inv[gw] = inv;
        float s = inv * QSCALE;
        char4* q4 = (char4*)(g_q + (size_t)gw * DIM);
#pragma unroll
        for (int u = 0; u < 6; u++) {
            char4 q;
            q.x = (char)__float2int_rn(fmaxf(fminf(v[u].x * s, 127.f), -127.f));
            q.y = (char)__float2int_rn(fmaxf(fminf(v[u].y * s, 127.f), -127.f));
            q.z = (char)__float2int_rn(fmaxf(fminf(v[u].z * s, 127.f), -127.f));
            q.w = (char)__float2int_rn(fmaxf(fminf(v[u].w * s, 127.f), -127.f));
            q4[u * 32 + lane] = q;
        }
    } else {
        __shared__ float s[32][33];
        int bb = b - NORMB;
        int m = bb / TTILES;
        int rem = bb % TTILES;
        int kx = rem % (DIM / 32), oy = rem / (DIM / 32);
        const float* W = (m == 0) ? W1 : (m == 1 ? W2 : W3);
        int tx = t & 31, ty = t >> 5;    // 32 x 8
        int k0 = kx * 32, o0 = oy * 32;
#pragma unroll
        for (int j = 0; j < 32; j += 8)
            s[ty + j][tx] = W[(size_t)(o0 + ty + j) * DIM + (k0 + tx)];
        __syncthreads();
#pragma unroll
        for (int j = 0; j < 32; j += 8)
            g_WT[m][(size_t)(k0 + ty + j) * DIM + (o0 + tx)] = s[tx][ty + j];
    }
}

// ---------------- kernel 2: int8 detector (proven R6 config, untouched) ----------------
__global__ void __launch_bounds__(256, 2) kdet() {
    int lin = blockIdx.x, d = blockIdx.z;
    int bx = (int)((sqrtf(8.f * (float)lin + 1.f) - 1.f) * 0.5f);
    while ((bx + 1) * (bx + 2) / 2 <= lin) bx++;
    while (bx * (bx + 1) / 2 > lin) bx--;
    int by = lin - bx * (bx + 1) / 2;

    __shared__ __align__(128) unsigned char As[STAGES][BM * BKB];
    __shared__ __align__(128) unsigned char Bs[STAGES][BM * BKB];

    int t = threadIdx.x, wid = t >> 5, lane = t & 31;
    int wm = wid & 1;        // 2 warps along M (64 rows each)
    int wn = wid >> 1;       // 4 warps along N (32 cols each)

    const int8_t* Ag = g_q + ((size_t)d * NTOK + (size_t)bx * BM) * DIM;
    const int8_t* Bg = g_q + ((size_t)d * NTOK + (size_t)by * BN) * DIM;

    uint32_t AsA[STAGES], BsA[STAGES];
#pragma unroll
    for (int s = 0; s < STAGES; s++) { AsA[s] = smem_u32(As[s]); BsA[s] = smem_u32(Bs[s]); }

    int rowq[2], segq[2];
    uint32_t soffq[2];
#pragma unroll
    for (int u = 0; u < 2; u++) {
        int q = t + 256 * u;
        rowq[u] = q >> 2; segq[u] = q & 3;
        soffq[u] = SW64((uint32_t)(rowq[u] * 64 + segq[u] * 16));
    }

#pragma unroll
    for (int s = 0; s < STAGES - 1; s++) {
        int k0 = s * BKB;
#pragma unroll
        for (int u = 0; u < 2; u++) {
            cp16(AsA[s] + soffq[u], Ag + (size_t)rowq[u] * DIM + k0 + segq[u] * 16);
            cp16(BsA[s] + soffq[u], Bg + (size_t)rowq[u] * DIM + k0 + segq[u] * 16);
        }
        CP_COMMIT();
    }

    int acc[4][4][4];
#pragma unroll
    for (int mi = 0; mi < 4; mi++)
#pragma unroll
        for (int ni = 0; ni < 4; ni++)
#pragma unroll
            for (int e = 0; e < 4; e++) acc[mi][ni][e] = 0;

    int cur = 0;
    for (int kb = 0; kb < KITER; kb++) {
        CP_WAIT1();
        __syncthreads();
        int nk = kb + STAGES - 1;
        if (nk < KITER) {
            int s = nk % STAGES;
            int k0 = nk * BKB;
#pragma unroll
            for (int u = 0; u < 2; u++) {
                cp16(AsA[s] + soffq[u], Ag + (size_t)rowq[u] * DIM + k0 + segq[u] * 16);
                cp16(BsA[s] + soffq[u], Bg + (size_t)rowq[u] * DIM + k0 + segq[u] * 16);
            }
        }
        CP_COMMIT();

#pragma unroll
        for (int ks = 0; ks < 2; ks++) {
            uint32_t af[4][4];
#pragma unroll
            for (int mi = 0; mi < 4; mi++) {
                int row = wm * 64 + mi * 16 + (lane & 15);
                int bcol = ks * 32 + ((lane >> 4) << 4);
                uint32_t addr = AsA[cur] + SW64((uint32_t)(row * 64 + bcol));
                ldm_x4(af[mi][0], af[mi][1], af[mi][2], af[mi][3], addr);
            }
            uint32_t bfr[4][2];
#pragma unroll
            for (int pair = 0; pair < 2; pair++) {
                int g = lane >> 3;
                int row = wn * 32 + pair * 16 + ((g >> 1) << 3) + (lane & 7);
                int bcol = ks * 32 + ((g & 1) << 4);
                uint32_t addr = BsA[cur] + SW64((uint32_t)(row * 64 + bcol));
                uint32_t r0, r1, r2, r3;
                ldm_x4(r0, r1, r2, r3, addr);
                bfr[pair * 2][0] = r0; bfr[pair * 2][1] = r1;
                bfr[pair * 2 + 1][0] = r2; bfr[pair * 2 + 1][1] = r3;
            }
#pragma unroll
            for (int mi = 0; mi < 4; mi++)
#pragma unroll
                for (int ni = 0; ni < 4; ni++)
                    imma16832(acc[mi][ni], af[mi], bfr[ni]);
        }
        cur = (cur + 1) % STAGES;
    }

    int i_base = bx * BM + wm * 64;
    int j_base = by * BN + wn * 32;
#pragma unroll
    for (int mi = 0; mi < 4; mi++) {
#pragma unroll
        for (int ni = 0; ni < 4; ni++) {
#pragma unroll
            for (int e = 0; e < 4; e++) {
                if (acc[mi][ni][e] > ITHRESH) {
                    int i = i_base + mi * 16 + (lane >> 2) + ((e >> 1) << 3);
                    int j = j_base + ni * 8 + ((lane & 3) << 1) + (e & 1);
                    if (i > j) {
                        int idx = atomicAdd(&g_cc, 1);
                        if (idx < CCAP) { g_cd[idx] = d; g_ci[idx] = i; g_cj[idx] = j; }
                    }
                }
            }
        }
    }
}

// ---------------- kernel 3: fused rescore + prep (8 blocks x 256 thr) ----------------
__global__ void kprep2(const float* __restrict__ emb) {
    int d = blockIdx.x, t = threadIdx.x, wid = t >> 5, lane = t & 31;
    __shared__ int   cidx[256];
    __shared__ float csim[256];
    __shared__ int   s_nc;

    // collect this doc's candidates
    if (t == 0) {
        int C = g_cc; if (C > CCAP) C = CCAP;
        int n = 0;
        for (int c = 0; c < C && n < 256; c++)
            if (g_cd[c] == d) cidx[n++] = c;
        s_nc = n;
    }
    __syncthreads();

    // exact fp32 rescore, one warp per candidate
    int nc = s_nc;
    for (int cc = wid; cc < nc; cc += 8) {
        int i = g_ci[cidx[cc]], j = g_cj[cidx[cc]];
        const float* ei = emb + ((size_t)d * NTOK + i) * DIM;
        const float* ej = emb + ((size_t)d * NTOK + j) * DIM;
        float a = 0.f;
        for (int k = lane; k < DIM; k += 32) a += ei[k] * ej[k];
#pragma unroll
        for (int o = 16; o > 0; o >>= 1) a += __shfl_xor_sync(0xffffffffu, a, o);
        if (lane == 0)
            csim[cc] = a * g_inv[d * NTOK + i] * g_inv[d * NTOK + j];
    }
    __syncthreads();

    // deterministic sort + CSR (thread 0; np tiny)
    if (t == 0) {
        int pi2[512], pj2[512];
        float ps2[512];
        int np = 0;
        for (int cc = 0; cc < nc && np + 1 < 512; cc++) {
            float s = csim[cc];
            if (s > SIM_THRESH) {
                int i = g_ci[cidx[cc]], j = g_cj[cidx[cc]];
                pi2[np] = i; pj2[np] = j; ps2[np] = s; np++;
                pi2[np] = j; pj2[np] = i; ps2[np] = s; np++;
            }
        }
        for (int a = 1; a < np; a++) {
            int ii = pi2[a], jj = pj2[a]; float ss = ps2[a];
            long key = (long)ii * NTOK + jj;
            int b = a - 1;
            while (b >= 0 && (long)pi2[b] * NTOK + pj2[b] > key) {
                pi2[b + 1] = pi2[b]; pj2[b + 1] = pj2[b]; ps2[b + 1] = ps2[b]; b--;
            }
            pi2[b + 1] = ii; pj2[b + 1] = jj; ps2[b + 1] = ss;
        }
        int ns = 0;
        for (int p = 0; p < np; p++) {
            if (ns == 0 || g_rows[d][ns - 1] != pi2[p]) {
                if (ns < RCAP) { g_rows[d][ns] = pi2[p]; g_rowptr[d][ns] = p; ns++; }
            }
            g_dpj[d][p] = pj2[p];
            g_dps[d][p] = ps2[p];
        }
        g_rowptr[d][ns] = np;
        for (int p = 0; p < np; p++) {
            int lo = 0, hi = ns - 1, f = -1, v = pj2[p];
            while (lo <= hi) {
                int mid = (lo + hi) >> 1; int rv = g_rows[d][mid];
                if (rv == v) { f = mid; break; }
                if (rv < v) lo = mid + 1; else hi = mid - 1;
            }
            g_djx[d][p] = f;
        }
        g_ns[d] = ns;
    }
}

// ---------------- kernel 4: one GNN layer on special rows (R6 structure) ----------------
__global__ void klayer(int l, const float* __restrict__ emb,
                       const float* __restrict__ bprev, const float* __restrict__ bcur) {
    int d = blockIdx.y, cx = blockIdx.x, t = threadIdx.x;  // 128 threads
    int ns = g_ns[d];
    if (ns == 0) return;
    __shared__ float y[DIM];
    const float* WT = g_WT[l];
    int rd = (l + 1) & 1;
    int wr = l & 1;
    for (int ii = 0; ii < ns; ii++) {
        for (int k = t; k < DIM; k += 128) {
            float a = 0.f;
            int p0 = g_rowptr[d][ii], p1 = g_rowptr[d][ii + 1];
            for (int p = p0; p < p1; p++) {
                float v;
                if (l == 0) {
                    v = emb[((size_t)d * NTOK + g_dpj[d][p]) * DIM + k];
                } else {
                    int jx = g_djx[d][p];
                    v = (jx >= 0) ? g_h[rd][d][jx][k] : fmaxf(bprev[k], 0.f);
                }
                a += g_dps[d][p] * v;
            }
            y[k] = a;
        }
        __syncthreads();
        int c = cx * 128 + t;
        float acc = bcur[c];
#pragma unroll 16
        for (int k = 0; k < DIM; k++) acc = fmaf(y[k], WT[(size_t)k * DIM + c], acc);
        g_h[wr][d][ii][c] = fmaxf(acc, 0.f);
        __syncthreads();
    }
}

// ---------------- kernel 5: output mean ----------------
__global__ void kout(const float* __restrict__ b3, float* __restrict__ out) {
    int d = blockIdx.x, t = threadIdx.x;  // 768 threads
    float c3 = fmaxf(b3[t], 0.f);
    float acc = c3;
    int ns = g_ns[d];
    for (int ii = 0; ii < ns; ii++)
        acc += (g_h[0][d][ii][t] - c3) * (1.0f / (float)NTOK);
    out[(size_t)d * DIM + t] = acc;
}

// ---------------- launch ----------------
extern "C" void kernel_launch(void* const* d_in, const int* in_sizes, int n_in,
                              void* d_out, int out_size) {
    const float* emb = (const float*)d_in[0];
    const float* W1  = (const float*)d_in[1];
    const float* b1  = (const float*)d_in[2];
    const float* W2  = (const float*)d_in[3];
    const float* b2  = (const float*)d_in[4];
    const float* W3  = (const float*)d_in[5];
    const float* b3  = (const float*)d_in[6];
    float* out = (float*)d_out;

    knormtrans<<<NORMB + 3 * TTILES, 256>>>(emb, W1, W2, W3);
    int nblk = NTOK / BM;                       // 32
    dim3 g(nblk * (nblk + 1) / 2, 1, BATCH);    // 528 x 8
    kdet<<<g, 256>>>();
    kprep2<<<BATCH, 256>>>(emb);
    klayer<<<dim3(6, BATCH), 128>>>(0, emb, b1, b1);
    klayer<<<dim3(6, BATCH), 128>>>(1, emb, b1, b2);
    klayer<<<dim3(6, BATCH), 128>>>(2, emb, b2, b3);
    kout<<<BATCH, DIM>>>(b3, out);
}